// round 8
// baseline (speedup 1.0000x reference)
#include <cuda_runtime.h>
#include <math.h>

// Problem constants
#define B_    32
#define S_    4096
#define I_    64
#define R_    1024
#define O_    8
#define KEXT  1088                 // R + I unified feature length
#define K2EXT (KEXT / 2)           // 544 k-pairs
#define NCTA  128
#define NTHREADS 512
#define NWARP 16
#define SLAB  (KEXT * B_)          // floats per timestep slab (34816)

// Batch-split tiling: CTA = (cg, bg); 32 col-groups x 4 batch-groups
#define CPB   32                   // cols per CTA
#define BPB   8                    // batches per CTA
#define NBG   4                    // batch groups (independent through phase 1)
#define NCG   32                   // col groups
#define K2R   512                  // r-part k-pairs
#define K2RPW (K2R / NWARP)        // 32 r k-pairs per warp
#define K2RPH (K2RPW / 2)          // 16 k-pairs per producer half
#define K2XPW ((K2EXT - K2R) / NWARP) // 2 x k-pairs per warp
#define K2PW  (K2EXT / NWARP)      // 34 k-pairs per warp (phase 2)

// Weight SMEM geometry (bank-conflict-free): row = 4 group slots of 80B (10 ull)
#define WROW  40                   // ull per k2 row (320 B)
#define WS_ULL (K2EXT * WROW)      // 21760 ull = 174080 B
#define REDSTR 12                  // floats per red row (48 B, 16B-aligned)
#define RED_F  (NWARP * B_ * REDSTR)          // 6144 floats = 24576 B per buffer
#define SMEM_BYTES (WS_ULL * 8 + 2 * RED_F * 4)   // 223232 B (ping-pong red)

typedef unsigned long long ull;

// State scratch, k-PAIRED layout:
//   float (k, b) of slab t at  t*SLAB + (k>>1)*64 + b*2 + (k&1)
//   ull word (k2, b) at (t*SLAB)/2 + k2*32 + b
//   k <  1024 : reservoir state r_{t-1}   (slab 0 r-part = 0)
//   k >= 1024 : input drive x[b][t][k-1024]
__device__ float g_rv[(size_t)(S_ + 1) * SLAB];   // ~571 MB
__device__ unsigned g_bar;                        // phase-transition grid barrier
// Point-to-point progress flags: flag (bg, cg) = steps published by CTA (cg,bg).
// Single writer each; one 128B line apiece.
__device__ unsigned g_flag[NBG * NCG * 32];

__global__ void esn_init_kernel() {
    int i = threadIdx.x;
    if (i == 0) g_bar = 0u;
    for (int e = i; e < NBG * NCG * 32; e += blockDim.x) g_flag[e] = 0u;
}

__device__ __forceinline__ void ffma2(ull& d, ull a, ull b) {
    asm("fma.rn.f32x2 %0, %1, %2, %0;" : "+l"(d) : "l"(a), "l"(b));
}
__device__ __forceinline__ float2 unpack2(ull v) {
    float2 r; asm("mov.b64 {%0, %1}, %2;" : "=f"(r.x), "=f"(r.y) : "l"(v)); return r;
}
__device__ __forceinline__ ull pack2(float lo, float hi) {
    return ((ull)__float_as_uint(hi) << 32) | (ull)__float_as_uint(lo);
}

// Single-writer store-release flag publish / acquire poll.
__device__ __forceinline__ void st_release(unsigned* p, unsigned v) {
    asm volatile("st.release.gpu.global.u32 [%0], %1;" :: "l"(p), "r"(v) : "memory");
}
__device__ __forceinline__ unsigned ld_acquire(const unsigned* p) {
    unsigned v;
    asm volatile("ld.acquire.gpu.global.u32 %0, [%1];" : "=r"(v) : "l"(p) : "memory");
    return v;
}
__device__ __forceinline__ void red_release_add(unsigned* p) {
    asm volatile("red.release.gpu.global.add.u32 [%0], 1;" :: "l"(p) : "memory");
}
__device__ __forceinline__ void grid_arrive() {
    __syncthreads();
    if (threadIdx.x == 0) red_release_add(&g_bar);
}
__device__ __forceinline__ void grid_wait(unsigned target) {
    if (threadIdx.x == 0) { while (ld_acquire(&g_bar) < target) { } }
    __syncthreads();
}
// Warp-local flag wait: no CTA sync — warps decouple across the step edge.
__device__ __forceinline__ void flag_wait(const unsigned* f, unsigned target) {
    while (ld_acquire(f) < target) { }
}

// Named barriers (id 0 reserved for __syncthreads)
#define BAR_SYNC(id, n)   asm volatile("bar.sync %0, %1;"   :: "r"(id), "r"(n) : "memory")
#define BAR_ARRIVE(id, n) asm volatile("bar.arrive %0, %1;" :: "r"(id), "r"(n) : "memory")

__global__ __launch_bounds__(NTHREADS, 1)
void esn_kernel(const float* __restrict__ x,
                const float* __restrict__ Win,
                const float* __restrict__ Wres,
                const float* __restrict__ Wout,
                float* __restrict__ out)
{
    extern __shared__ __align__(16) char smem[];
    ull*   Ws   = reinterpret_cast<ull*>(smem);
    float* red0 = reinterpret_cast<float*>(smem + WS_ULL * 8);   // parity 0
    float* red1 = red0 + RED_F;                                  // parity 1

    const int tid  = threadIdx.x;
    const int cta  = blockIdx.x;
    const int warp = tid >> 5;
    const int lane = tid & 31;
    const int cg   = cta >> 2;           // col group 0..31  -> cols cg*32..+32
    const int bg   = cta & 3;            // batch group 0..3 -> batches bg*8..+8
    const int grp  = lane >> 3;          // col sub-group 0..3
    const int bl   = lane & 7;           // local batch 0..7
    const bool is_reducer = (warp < 8);  // warps 0-7 reduce; 8-15 run ahead

    unsigned* my_flag = &g_flag[(bg * NCG + cg) * 32];
    unsigned* fA      = &g_flag[(bg * NCG + 2 * warp) * 32];     // cols [64w,64w+32)
    unsigned* fB      = &g_flag[(bg * NCG + 2 * warp + 1) * 32]; // cols [64w+32,64w+64)

    // ---- Stage recurrence weights, padded-group layout:
    //   Ws[k2*40 + (cl>>3)*10 + (cl&7)] = { w(2k2,c), w(2k2+1,c) }, c = cg*32+cl
    //   w(k,c) = k<R ? Wres[c][k] : Win[c][k-R]
    for (int idx = tid; idx < K2EXT * CPB; idx += NTHREADS) {
        int k2 = idx >> 5, cl = idx & 31, c = cg * CPB + cl;
        int k0 = 2 * k2, k1 = 2 * k2 + 1;
        float w0 = (k0 < R_) ? Wres[(size_t)c * R_ + k0] : Win[(size_t)c * I_ + (k0 - R_)];
        float w1 = (k1 < R_) ? Wres[(size_t)c * R_ + k1] : Win[(size_t)c * I_ + (k1 - R_)];
        Ws[k2 * WROW + (cl >> 3) * 10 + (cl & 7)] = pack2(w0, w1);
    }

    // ---- Phase 0: zero slab-0 r-part; transpose x into paired layout
    {
        int g = cta * NTHREADS + tid;
        if (g < R_ * B_) g_rv[g] = 0.0f;         // slab-0 r-part (32768 floats)
        for (size_t e = g; e < (size_t)S_ * B_ * I_; e += (size_t)NCTA * NTHREADS) {
            int i = (int)(e & (I_ - 1));
            size_t tb = e >> 6;
            int b = (int)(tb & (B_ - 1));
            int t = (int)(tb >> 5);
            int k = R_ + i;
            g_rv[(size_t)t * SLAB + (size_t)(k >> 1) * 64 + b * 2 + (k & 1)] =
                x[(size_t)b * (S_ * I_) + (size_t)t * I_ + i];
        }
    }

    grid_arrive();
    grid_wait(NCTA);                             // x-drive + r_0 visible everywhere

    // ---- Phase 1: sequential recurrence; producers run ahead, reducers own tail
    const int rbeg = warp * K2RPW;
    const int xbeg = K2R + warp * K2XPW;
    const int b0   = bg * BPB;

    for (int t = 0; t < S_; t++) {
        const ull* __restrict__ rvt =
            reinterpret_cast<const ull*>(g_rv + (size_t)t * SLAB);
        float* redc = (t & 1) ? red1 : red0;     // this step's partials buffer

        ull acc[BPB];
        #pragma unroll
        for (int j = 0; j < BPB; j++) acc[j] = 0ull;

        // x-prelude: input drive, independent of r_t -> before any wait
        #pragma unroll
        for (int kk = 0; kk < K2XPW; kk++) {
            int k2 = xbeg + kk;
            ull v = rvt[k2 * B_ + b0 + bl];
            const ulonglong2* wr =
                reinterpret_cast<const ulonglong2*>(Ws + k2 * WROW + grp * 10);
            ulonglong2 w01 = wr[0], w23 = wr[1], w45 = wr[2], w67 = wr[3];
            ffma2(acc[0], v, w01.x); ffma2(acc[1], v, w01.y);
            ffma2(acc[2], v, w23.x); ffma2(acc[3], v, w23.y);
            ffma2(acc[4], v, w45.x); ffma2(acc[5], v, w45.y);
            ffma2(acc[6], v, w67.x); ffma2(acc[7], v, w67.y);
        }

        // First producer half: cols of cg = 2*warp
        flag_wait(fA, (unsigned)t);
        #pragma unroll 8
        for (int kk = 0; kk < K2RPH; kk++) {
            int k2 = rbeg + kk;
            ull v = rvt[k2 * B_ + b0 + bl];                    // 64B/warp, L2-hot
            const ulonglong2* wr =
                reinterpret_cast<const ulonglong2*>(Ws + k2 * WROW + grp * 10);
            ulonglong2 w01 = wr[0], w23 = wr[1], w45 = wr[2], w67 = wr[3];
            ffma2(acc[0], v, w01.x); ffma2(acc[1], v, w01.y);
            ffma2(acc[2], v, w23.x); ffma2(acc[3], v, w23.y);
            ffma2(acc[4], v, w45.x); ffma2(acc[5], v, w45.y);
            ffma2(acc[6], v, w67.x); ffma2(acc[7], v, w67.y);
        }

        // Second producer half: cols of cg = 2*warp+1 (poll overlapped by above)
        flag_wait(fB, (unsigned)t);
        #pragma unroll 8
        for (int kk = K2RPH; kk < K2RPW; kk++) {
            int k2 = rbeg + kk;
            ull v = rvt[k2 * B_ + b0 + bl];
            const ulonglong2* wr =
                reinterpret_cast<const ulonglong2*>(Ws + k2 * WROW + grp * 10);
            ulonglong2 w01 = wr[0], w23 = wr[1], w45 = wr[2], w67 = wr[3];
            ffma2(acc[0], v, w01.x); ffma2(acc[1], v, w01.y);
            ffma2(acc[2], v, w23.x); ffma2(acc[3], v, w23.y);
            ffma2(acc[4], v, w45.x); ffma2(acc[5], v, w45.y);
            ffma2(acc[6], v, w67.x); ffma2(acc[7], v, w67.y);
        }

        // Buffer-reuse guard: writing step-t partials into buffer (t&1) needs
        // own CTA's reduce of step t-2 complete  <=>  my_flag >= t-1.
        if (t >= 2) flag_wait(my_flag, (unsigned)(t - 1));

        // Publish partials: (col = grp*8+j, batch = b0+bl) -> 2 STS.128
        {
            float s[BPB];
            #pragma unroll
            for (int j = 0; j < BPB; j++) {
                float2 h = unpack2(acc[j]);
                s[j] = h.x + h.y;
            }
            float4* myred =
                reinterpret_cast<float4*>(redc + (warp * B_ + lane) * REDSTR);
            myred[0] = make_float4(s[0], s[1], s[2], s[3]);
            myred[1] = make_float4(s[4], s[5], s[6], s[7]);
        }

        if (!is_reducer) {
            BAR_ARRIVE(1, NTHREADS);             // hand off; run ahead into t+1
            continue;
        }

        // ---- Reducer warps (0-7): tail of step t
        BAR_SYNC(1, NTHREADS);                   // all 16 warps' STS drained

        {   // thread tid (0..255) owns output (cl = tid>>3, b = tid&7)
            int cl = tid >> 3, bo = tid & 7;
            int rl = (cl >> 3) * 8 + bo;         // lane that accumulated it
            int j  = cl & 7;
            float s = 0.0f;
            #pragma unroll
            for (int w = 0; w < NWARP; w++)
                s += redc[(w * B_ + rl) * REDSTR + j];
            float r = tanhf(s);
            int c = cg * CPB + cl, b = b0 + bo;
            g_rv[(size_t)(t + 1) * SLAB + (size_t)(c >> 1) * 64 + b * 2 + (c & 1)] = r;
        }

        BAR_SYNC(3, 256);                        // reducer join: r-stores ordered
        if (tid == 0) st_release(my_flag, (unsigned)(t + 1));
    }

    // ---- Grid-wide barrier before readout (all groups' r complete)
    grid_arrive();
    grid_wait(2 * NCTA);

    // ---- Phase 2: readout. Restage Ws head as Wout pairs [k2][o]:
    //   k<R pairs r (Wout[o][64+k]); k>=R pairs x (Wout[o][k-1024])
    for (int idx = tid; idx < K2EXT * O_; idx += NTHREADS) {
        int k2 = idx >> 3, o = idx & 7;
        int k0 = 2 * k2, k1 = 2 * k2 + 1;
        float w0 = (k0 < R_) ? Wout[(size_t)o * KEXT + I_ + k0]
                             : Wout[(size_t)o * KEXT + (k0 - R_)];
        float w1 = (k1 < R_) ? Wout[(size_t)o * KEXT + I_ + k1]
                             : Wout[(size_t)o * KEXT + (k1 - R_)];
        Ws[k2 * 8 + o] = pack2(w0, w1);
    }
    __syncthreads();

    const int kbeg2 = warp * K2PW;               // 34 k-pairs per warp
    for (int s = cta; s < S_; s += NCTA) {
        const ull* __restrict__ rv_r =
            reinterpret_cast<const ull*>(g_rv + (size_t)(s + 1) * SLAB);  // r_s
        const ull* __restrict__ rv_x =
            reinterpret_cast<const ull*>(g_rv + (size_t)s * SLAB);        // x_s

        ull acc[O_];
        #pragma unroll
        for (int o = 0; o < O_; o++) acc[o] = 0ull;

        #pragma unroll 8
        for (int kk = 0; kk < K2PW; kk++) {
            int k2 = kbeg2 + kk;
            const ull* src = (k2 < K2R) ? rv_r : rv_x;
            ull v = src[k2 * B_ + lane];                       // lane = batch
            const ulonglong2* wr =
                reinterpret_cast<const ulonglong2*>(Ws + k2 * 8);
            ulonglong2 w01 = wr[0], w23 = wr[1], w45 = wr[2], w67 = wr[3];
            ffma2(acc[0], v, w01.x); ffma2(acc[1], v, w01.y);
            ffma2(acc[2], v, w23.x); ffma2(acc[3], v, w23.y);
            ffma2(acc[4], v, w45.x); ffma2(acc[5], v, w45.y);
            ffma2(acc[6], v, w67.x); ffma2(acc[7], v, w67.y);
        }

        {
            float sv[O_];
            #pragma unroll
            for (int o = 0; o < O_; o++) {
                float2 h = unpack2(acc[o]);
                sv[o] = h.x + h.y;
            }
            float4* myred =
                reinterpret_cast<float4*>(red0 + (warp * B_ + lane) * REDSTR);
            myred[0] = make_float4(sv[0], sv[1], sv[2], sv[3]);
            myred[1] = make_float4(sv[4], sv[5], sv[6], sv[7]);
        }
        __syncthreads();
        if (tid < B_ * O_) {                     // 256 outputs: b = tid&31, o = tid>>5
            int b = tid & 31, o = tid >> 5;
            float v = 0.0f;
            #pragma unroll
            for (int w = 0; w < NWARP; w++)
                v += red0[(w * B_ + b) * REDSTR + o];
            out[(size_t)b * (S_ * O_) + (size_t)s * O_ + o] = v;
        }
        __syncthreads();
    }
}

extern "C" void kernel_launch(void* const* d_in, const int* in_sizes, int n_in,
                              void* d_out, int out_size) {
    const float* x    = (const float*)d_in[0];   // [32,4096,64]
    const float* Win  = (const float*)d_in[1];   // [1024,64]
    const float* Wres = (const float*)d_in[2];   // [1024,1024]
    const float* Wout = (const float*)d_in[3];   // [8,1088]
    float* out = (float*)d_out;                  // [32,4096,8]

    cudaFuncSetAttribute(esn_kernel,
                         cudaFuncAttributeMaxDynamicSharedMemorySize, SMEM_BYTES);
    esn_init_kernel<<<1, 256>>>();
    esn_kernel<<<NCTA, NTHREADS, SMEM_BYTES>>>(x, Win, Wres, Wout, out);
}

// round 12
// speedup vs baseline: 1.0966x; 1.0966x over previous
#include <cuda_runtime.h>
#include <math.h>

// Problem constants
#define B_    32
#define S_    4096
#define I_    64
#define R_    1024
#define O_    8
#define KEXT  1088
#define NCTA  128
#define NTHREADS 512
#define NWARP 16
#define SLAB  (KEXT * B_)              // floats per timestep slab (34816)
#define BGSTR (KEXT * 8)               // floats per batch-group block (8704)

// Tiling: CTA = (cg, bg); thread tile 4 cols x 8 batches (4 batch-pairs)
#define CPB   32
#define BPB   8
#define NBG   4
#define NCG   32
#define RQPW  16                       // r k-quads per warp (256/16)

// SMEM: WR = [1088][32] floats (128B rows) ; partials 2 x (16 warps x 144 ull)
#define WR_F   (KEXT * 32)             // 34816 floats = 139264 B
#define PART_ULL (NWARP * 144)         // 2304 ull = 18432 B per buffer
#define SMEM_BYTES (WR_F * 4 + 2 * PART_ULL * 8)   // 176128 B

typedef unsigned long long ull;

// State scratch: float (k, b) of slab t at
//   t*SLAB + (b>>3)*BGSTR + k*8 + (b&7)      (32B k-rows per batch group)
// k < 1024: reservoir r_{t-1} (slab0 zeroed); k >= 1024: x drive x[b][t][k-1024]
__device__ float g_rv[(size_t)(S_ + 1) * SLAB];   // ~571 MB
__device__ unsigned g_bar;
__device__ unsigned g_flag[NBG * NCG * 32];       // (bg,cg) progress, 128B apart

__global__ void esn_init_kernel() {
    int i = threadIdx.x;
    if (i == 0) g_bar = 0u;
    for (int e = i; e < NBG * NCG * 32; e += blockDim.x) g_flag[e] = 0u;
}

__device__ __forceinline__ void ffma2(ull& d, ull a, ull b) {
    asm("fma.rn.f32x2 %0, %1, %2, %0;" : "+l"(d) : "l"(a), "l"(b));
}
__device__ __forceinline__ ull addf32x2(ull a, ull b) {
    ull d; asm("add.rn.f32x2 %0, %1, %2;" : "=l"(d) : "l"(a), "l"(b)); return d;
}
__device__ __forceinline__ ull dup2(float w) {        // {w, w} packed
    unsigned u = __float_as_uint(w); ull d;
    asm("mov.b64 %0, {%1, %2};" : "=l"(d) : "r"(u), "r"(u));
    return d;
}
__device__ __forceinline__ ull shfl_down_u64(ull v, int delta) {
    unsigned lo = (unsigned)v, hi = (unsigned)(v >> 32);
    lo = __shfl_down_sync(0xffffffffu, lo, delta);
    hi = __shfl_down_sync(0xffffffffu, hi, delta);
    return ((ull)hi << 32) | lo;
}

__device__ __forceinline__ void st_release(unsigned* p, unsigned v) {
    asm volatile("st.release.gpu.global.u32 [%0], %1;" :: "l"(p), "r"(v) : "memory");
}
__device__ __forceinline__ unsigned ld_acquire(const unsigned* p) {
    unsigned v;
    asm volatile("ld.acquire.gpu.global.u32 %0, [%1];" : "=r"(v) : "l"(p) : "memory");
    return v;
}
__device__ __forceinline__ void red_release_add(unsigned* p) {
    asm volatile("red.release.gpu.global.add.u32 [%0], 1;" :: "l"(p) : "memory");
}
__device__ __forceinline__ void grid_arrive() {
    __syncthreads();
    if (threadIdx.x == 0) red_release_add(&g_bar);
}
__device__ __forceinline__ void grid_wait(unsigned target) {
    if (threadIdx.x == 0) { while (ld_acquire(&g_bar) < target) { } }
    __syncthreads();
}
__device__ __forceinline__ void flag_wait(const unsigned* f, unsigned target) {
    while (ld_acquire(f) < target) { }
}

#define BAR_SYNC(id, n)   asm volatile("bar.sync %0, %1;"   :: "r"(id), "r"(n) : "memory")
#define BAR_ARRIVE(id, n) asm volatile("bar.arrive %0, %1;" :: "r"(id), "r"(n) : "memory")

__global__ __launch_bounds__(NTHREADS, 1)
void esn_kernel(const float* __restrict__ x,
                const float* __restrict__ Win,
                const float* __restrict__ Wres,
                const float* __restrict__ Wout,
                float* __restrict__ out)
{
    extern __shared__ __align__(16) char smem[];
    float* WRf   = reinterpret_cast<float*>(smem);              // [k][32 cols]
    ull*   part0 = reinterpret_cast<ull*>(smem + WR_F * 4);
    ull*   part1 = part0 + PART_ULL;

    const int tid  = threadIdx.x;
    const int cta  = blockIdx.x;
    const int warp = tid >> 5;
    const int lane = tid & 31;
    const int cg   = cta >> 2;          // cols cg*32..+32
    const int bg   = cta & 3;           // batches bg*8..+8
    const int kk   = lane >> 3;         // sub-k within quad 0..3
    const int cq   = lane & 7;          // col quad: cols 4cq..4cq+3

    unsigned* my_flag = &g_flag[(bg * NCG + cg) * 32];
    unsigned* fA = &g_flag[(bg * NCG + 2 * warp) * 32];      // k-cols [64w, 64w+32)
    unsigned* fB = &g_flag[(bg * NCG + 2 * warp + 1) * 32];  // k-cols [64w+32, 64w+64)

    // ---- Stage weights: WRf[k*32 + c] = k<1024 ? Wres[col][k] : Win[col][k-1024]
    for (int idx = tid; idx < KEXT * CPB; idx += NTHREADS) {
        int k = idx >> 5, c = idx & 31, col = cg * CPB + c;
        WRf[k * 32 + c] = (k < R_) ? Wres[(size_t)col * R_ + k]
                                   : Win[(size_t)col * I_ + (k - R_)];
    }

    // ---- Phase 0: zero slab-0 r-part; transpose x
    {
        int g = cta * NTHREADS + tid;
        if (g < R_ * B_) {
            int bgz = g >> 13, rest = g & 8191;
            g_rv[(size_t)bgz * BGSTR + rest] = 0.0f;
        }
        for (size_t e = g; e < (size_t)S_ * B_ * I_; e += (size_t)NCTA * NTHREADS) {
            int i = (int)(e & (I_ - 1));
            size_t tb = e >> 6;
            int b = (int)(tb & (B_ - 1));
            int t = (int)(tb >> 5);
            g_rv[(size_t)t * SLAB + (size_t)(b >> 3) * BGSTR +
                 (size_t)(R_ + i) * 8 + (b & 7)] =
                x[(size_t)b * (S_ * I_) + (size_t)t * I_ + i];
        }
    }

    grid_arrive();
    grid_wait(NCTA);

    // ---- Phase 1: sequential recurrence
    const bool is_reducer = (warp < 8);

#define KBODY(qq) { \
        int k_ = (qq) * 4 + kk; \
        float4 w4 = *reinterpret_cast<const float4*>(WRf + k_ * 32 + 4 * cq); \
        ull w0 = dup2(w4.x), w1 = dup2(w4.y), w2 = dup2(w4.z), w3 = dup2(w4.w); \
        const ulonglong2* sp = \
            reinterpret_cast<const ulonglong2*>(rvbg + (size_t)k_ * 8); \
        ulonglong2 sA = sp[0], sB = sp[1]; \
        ffma2(acc[0],  w0, sA.x); ffma2(acc[1],  w0, sA.y); \
        ffma2(acc[2],  w0, sB.x); ffma2(acc[3],  w0, sB.y); \
        ffma2(acc[4],  w1, sA.x); ffma2(acc[5],  w1, sA.y); \
        ffma2(acc[6],  w1, sB.x); ffma2(acc[7],  w1, sB.y); \
        ffma2(acc[8],  w2, sA.x); ffma2(acc[9],  w2, sA.y); \
        ffma2(acc[10], w2, sB.x); ffma2(acc[11], w2, sB.y); \
        ffma2(acc[12], w3, sA.x); ffma2(acc[13], w3, sA.y); \
        ffma2(acc[14], w3, sB.x); ffma2(acc[15], w3, sB.y); }

    for (int t = 0; t < S_; t++) {
        const float* rvbg = g_rv + (size_t)t * SLAB + (size_t)bg * BGSTR;
        ull* partc = (t & 1) ? part1 : part0;

        ull acc[16];
        #pragma unroll
        for (int a = 0; a < 16; a++) acc[a] = 0ull;

        // x-prelude: x-quad (256 + warp), independent of r_t
        KBODY(256 + warp)

        flag_wait(fA, (unsigned)t);
        #pragma unroll
        for (int j = 0; j < 8; j++) KBODY(warp * RQPW + j)

        flag_wait(fB, (unsigned)t);
        #pragma unroll
        for (int j = 8; j < 16; j++) KBODY(warp * RQPW + j)

        // fold kk (lanes 8 apart): lanes 0..7 (=cq) hold warp totals
        #pragma unroll
        for (int a = 0; a < 16; a++) acc[a] = addf32x2(acc[a], shfl_down_u64(acc[a], 16));
        #pragma unroll
        for (int a = 0; a < 16; a++) acc[a] = addf32x2(acc[a], shfl_down_u64(acc[a], 8));

        // Publish guard — PRODUCERS ONLY. Producers skip the barrier sync, so
        // before writing step-t partials / arriving at barrier 1 they need own
        // reduce of t-1 complete (my_flag >= t):
        //  (a) parity-t buffer free, (b) barrier-1 phase t-1 released -> no
        //      double-arrival within one phase.
        // Reducer warps proved both via their own BAR_SYNCs of step t-1; the
        // poll would be a pure L2 round-trip on the reduce critical path.
        if (!is_reducer && t >= 1) flag_wait(my_flag, (unsigned)t);

        if (lane < 8) {
            ulonglong2* pv = reinterpret_cast<ulonglong2*>(partc + warp * 144 + lane * 18);
            #pragma unroll
            for (int i = 0; i < 8; i++) {
                ulonglong2 v2; v2.x = acc[2 * i]; v2.y = acc[2 * i + 1];
                pv[i] = v2;
            }
        }

        if (!is_reducer) { BAR_ARRIVE(1, NTHREADS); continue; }

        BAR_SYNC(1, NTHREADS);
        {   // reducer thread tid<256 owns output (c = tid>>3, b = tid&7)
            int c = tid >> 3, b = tid & 7;
            int a = (c & 3) * 4 + (b >> 1);
            const float* pf = reinterpret_cast<const float*>(partc) +
                              ((c >> 2) * 18 + a) * 2 + (b & 1);
            float s = 0.0f;
            #pragma unroll
            for (int w = 0; w < NWARP; w++) s += pf[w * 288];
            float r = tanhf(s);
            g_rv[(size_t)(t + 1) * SLAB + (size_t)bg * BGSTR +
                 (size_t)(cg * CPB + c) * 8 + b] = r;
        }
        BAR_SYNC(3, 256);
        if (tid == 0) st_release(my_flag, (unsigned)(t + 1));
    }
#undef KBODY

    grid_arrive();
    grid_wait(2 * NCTA);

    // ---- Phase 2: readout (reuse smem: W2 = [k][8 o] floats; part2 after)
    float* W2 = reinterpret_cast<float*>(smem);
    ull* part2 = reinterpret_cast<ull*>(smem + KEXT * O_ * 4);
    for (int idx = tid; idx < KEXT * O_; idx += NTHREADS) {
        int k = idx >> 3, o = idx & 7;
        W2[k * 8 + o] = (k < R_) ? Wout[(size_t)o * KEXT + I_ + k]
                                 : Wout[(size_t)o * KEXT + (k - R_)];
    }
    __syncthreads();

    const int u = lane & 7;
    const int bg2 = u >> 1, hf = u & 1;
    for (int s = cta; s < S_; s += NCTA) {
        const float* base_r = g_rv + (size_t)(s + 1) * SLAB;
        const float* base_x = g_rv + (size_t)s * SLAB;

        ull acc2[16];
        #pragma unroll
        for (int a = 0; a < 16; a++) acc2[a] = 0ull;

        #pragma unroll 4
        for (int i = 0; i < 17; i++) {           // quads warp + 16*i
            int q = warp + 16 * i;
            int k = q * 4 + kk;
            const float* sb = (q < 256) ? base_r : base_x;
            ulonglong2 sv = *reinterpret_cast<const ulonglong2*>(
                sb + (size_t)bg2 * BGSTR + (size_t)k * 8 + hf * 4);
            const float4* wp = reinterpret_cast<const float4*>(W2 + k * 8);
            float4 wa = wp[0], wb = wp[1];
            ull W0 = dup2(wa.x), W1 = dup2(wa.y), W2u = dup2(wa.z), W3 = dup2(wa.w);
            ull W4 = dup2(wb.x), W5 = dup2(wb.y), W6 = dup2(wb.z), W7 = dup2(wb.w);
            ffma2(acc2[0],  W0, sv.x); ffma2(acc2[1],  W0, sv.y);
            ffma2(acc2[2],  W1, sv.x); ffma2(acc2[3],  W1, sv.y);
            ffma2(acc2[4],  W2u, sv.x); ffma2(acc2[5],  W2u, sv.y);
            ffma2(acc2[6],  W3, sv.x); ffma2(acc2[7],  W3, sv.y);
            ffma2(acc2[8],  W4, sv.x); ffma2(acc2[9],  W4, sv.y);
            ffma2(acc2[10], W5, sv.x); ffma2(acc2[11], W5, sv.y);
            ffma2(acc2[12], W6, sv.x); ffma2(acc2[13], W6, sv.y);
            ffma2(acc2[14], W7, sv.x); ffma2(acc2[15], W7, sv.y);
        }

        #pragma unroll
        for (int a = 0; a < 16; a++) acc2[a] = addf32x2(acc2[a], shfl_down_u64(acc2[a], 16));
        #pragma unroll
        for (int a = 0; a < 16; a++) acc2[a] = addf32x2(acc2[a], shfl_down_u64(acc2[a], 8));

        if (lane < 8) {
            ulonglong2* pv = reinterpret_cast<ulonglong2*>(part2 + warp * 144 + lane * 18);
            #pragma unroll
            for (int i = 0; i < 8; i++) {
                ulonglong2 v2; v2.x = acc2[2 * i]; v2.y = acc2[2 * i + 1];
                pv[i] = v2;
            }
        }
        __syncthreads();
        if (tid < B_ * O_) {                 // o = tid>>5, b = tid&31
            int o = tid >> 5, b = tid & 31;
            int u2 = b >> 2, p = (b >> 1) & 1, h = b & 1;
            const float* pf = reinterpret_cast<const float*>(part2) +
                              (u2 * 18 + o * 2 + p) * 2 + h;
            float v = 0.0f;
            #pragma unroll
            for (int w = 0; w < NWARP; w++) v += pf[w * 288];
            out[(size_t)b * (S_ * O_) + (size_t)s * O_ + o] = v;
        }
        __syncthreads();
    }
}

extern "C" void kernel_launch(void* const* d_in, const int* in_sizes, int n_in,
                              void* d_out, int out_size) {
    const float* x    = (const float*)d_in[0];   // [32,4096,64]
    const float* Win  = (const float*)d_in[1];   // [1024,64]
    const float* Wres = (const float*)d_in[2];   // [1024,1024]
    const float* Wout = (const float*)d_in[3];   // [8,1088]
    float* out = (float*)d_out;                  // [32,4096,8]

    cudaFuncSetAttribute(esn_kernel,
                         cudaFuncAttributeMaxDynamicSharedMemorySize, SMEM_BYTES);
    esn_init_kernel<<<1, 256>>>();
    esn_kernel<<<NCTA, NTHREADS, SMEM_BYTES>>>(x, Win, Wres, Wout, out);
}